// round 4
// baseline (speedup 1.0000x reference)
#include <cuda_runtime.h>
#include <cuda_bf16.h>
#include <math.h>

// Problem constants (fixed shapes from reference setup_inputs):
//   cls_conv_out: (4, 21*49=1029, 100, 100) fp32 ; rois: (2000, 4) int32
//   Only batch index 3 is used. Output: (2000, 21, 1, 1) fp32.
#define KK        7
#define C1        21
#define NJL       49            // 7*7
#define H         100
#define W         100
#define HP        101           // padded
#define ROW_F     (HP * C1)     // floats per padded row in transposed layout = 2121
#define PLANE_F   (HP * ROW_F)  // floats per (j,l) plane = 101*2121
#define IN_BASE   (3 * 1029 * 10000)  // batch 3 offset in input

// Integral image, transposed layout: I[jl][y][x][c], c innermost (21 contiguous).
// 49 * 101 * 101 * 21 floats = ~42 MB static device scratch (allowed).
__device__ float g_integral[(size_t)NJL * PLANE_F];

// ---------------------------------------------------------------------------
// Kernel A: per (jl, padded-y) row: load 21 channel rows, x-cumsum each,
// write padded+transposed row [x][c] (x=0 column and y=0 row are zeros).
// ---------------------------------------------------------------------------
__global__ void build_xsum(const float* __restrict__ in) {
    const int y  = blockIdx.x;   // 0..100 (padded coord)
    const int jl = blockIdx.y;   // 0..48
    float* outrow = g_integral + ((size_t)jl * HP + y) * ROW_F;

    if (y == 0) {
        for (int i = threadIdx.x; i < ROW_F; i += blockDim.x) outrow[i] = 0.0f;
        return;
    }

    __shared__ float sm[C1 * HP];  // [c][x], padded stride 101 -> conflict-free
    const float* src = in + IN_BASE + (size_t)jl * C1 * (H * W) + (size_t)(y - 1) * W;

    for (int i = threadIdx.x; i < C1 * W; i += blockDim.x) {
        int c = i / W, xx = i % W;
        sm[c * HP + xx] = src[(size_t)c * (H * W) + xx];
    }
    __syncthreads();

    if (threadIdx.x < C1) {
        float acc = 0.0f;
        const int base = threadIdx.x * HP;
        #pragma unroll 4
        for (int xx = 0; xx < W; xx++) {
            acc += sm[base + xx];
            sm[base + xx] = acc;
        }
    }
    __syncthreads();

    for (int i = threadIdx.x; i < ROW_F; i += blockDim.x) {
        int xx = i / C1, c = i % C1;
        outrow[i] = (xx == 0) ? 0.0f : sm[c * HP + (xx - 1)];
    }
}

// ---------------------------------------------------------------------------
// Kernel B: y-cumsum in transposed layout. One (x,c) slot per thread,
// coalesced 128B/warp per y-step; only dependency is the FADD chain.
// ---------------------------------------------------------------------------
__global__ void build_ysum() {
    const int jl   = blockIdx.y;
    const int slot = blockIdx.x * blockDim.x + threadIdx.x;
    if (slot >= ROW_F) return;

    float* p = g_integral + (size_t)jl * PLANE_F + slot;
    float acc = 0.0f;
    #pragma unroll 5
    for (int y = 1; y <= H; y++) {
        float v = p[(size_t)y * ROW_F];
        acc += v;
        p[(size_t)y * ROW_F] = acc;
    }
}

// ---------------------------------------------------------------------------
// Kernel C: one block per ROI. 1029 (jl,c) slots; each reads 4 corners
// (84B contiguous across c per corner), deterministic smem reduction over jl,
// then warp softmax over 21 channels.
// ---------------------------------------------------------------------------
__global__ void pool_softmax(const int* __restrict__ rois,
                             float* __restrict__ out) {
    const int roi = blockIdx.x;
    __shared__ float s_S[NJL * C1];  // 1029 bin sums
    __shared__ float s_avg[C1];

    const int ymin = rois[roi * 4 + 0];
    const int xmin = rois[roi * 4 + 1];
    const int ymax = rois[roi * 4 + 2];
    const int xmax = rois[roi * 4 + 3];
    const int ys = (ymax - ymin) / KK;
    const int xs = (xmax - xmin) / KK;

    for (int i = threadIdx.x; i < NJL * C1; i += blockDim.x) {
        const int jl = i / C1, c = i % C1;
        const int j = jl / KK, l = jl % KK;
        const int y0 = ymin + j * ys, y1 = y0 + ys;
        const int x0 = xmin + l * xs, x1 = x0 + xs;
        const float* P = g_integral + (size_t)jl * PLANE_F;
        const float a = P[((size_t)y1 * HP + x1) * C1 + c];
        const float b = P[((size_t)y0 * HP + x1) * C1 + c];
        const float d = P[((size_t)y1 * HP + x0) * C1 + c];
        const float e = P[((size_t)y0 * HP + x0) * C1 + c];
        s_S[i] = (a - b) - (d - e);
    }
    __syncthreads();

    if (threadIdx.x < C1) {
        float acc = 0.0f;
        #pragma unroll 7
        for (int jl = 0; jl < NJL; jl++) acc += s_S[jl * C1 + threadIdx.x];
        s_avg[threadIdx.x] = acc / (49.0f * (float)(ys * xs));
    }
    __syncthreads();

    if (threadIdx.x < 32) {
        const bool act = threadIdx.x < C1;
        float v = act ? s_avg[threadIdx.x] : -INFINITY;
        float m = v;
        #pragma unroll
        for (int o = 16; o; o >>= 1) m = fmaxf(m, __shfl_xor_sync(0xffffffffu, m, o));
        float e = act ? __expf(v - m) : 0.0f;
        // use accurate expf for closeness to reference
        e = act ? expf(v - m) : 0.0f;
        float sum = e;
        #pragma unroll
        for (int o = 16; o; o >>= 1) sum += __shfl_xor_sync(0xffffffffu, sum, o);
        if (act) out[(size_t)roi * C1 + threadIdx.x] = e / sum;
    }
}

// ---------------------------------------------------------------------------
extern "C" void kernel_launch(void* const* d_in, const int* in_sizes, int n_in,
                              void* d_out, int out_size) {
    const float* x    = (const float*)d_in[0];
    const int*   rois = (const int*)d_in[1];
    float*       out  = (float*)d_out;
    const int n_rois = in_sizes[1] / 4;  // 2000

    dim3 gA(HP, NJL);                 // 101 x 49 blocks
    build_xsum<<<gA, 128>>>(x);

    dim3 gB((ROW_F + 255) / 256, NJL); // 9 x 49 blocks
    build_ysum<<<gB, 256>>>();

    pool_softmax<<<n_rois, 256>>>(rois, out);
}

// round 5
// speedup vs baseline: 1.1814x; 1.1814x over previous
#include <cuda_runtime.h>
#include <cuda_bf16.h>
#include <math.h>

// Fixed shapes: cls_conv_out (4, 1029, 100, 100) fp32; rois (2000,4) int32.
// Only batch 3 used. Output (2000, 21, 1, 1) fp32.
#define KK       7
#define C1       21
#define NJL      49
#define H        100
#define W        100
#define HP       101
#define ROW_S    2124                 // HP*C1 = 2121, padded to mult of 4 -> 16B aligned planes
#define PLANE_S  (HP * ROW_S)        // 214524 floats per (j,l) plane
#define IN_BASE  (3 * 1029 * 10000)  // batch 3 offset

// Integral image, transposed c-innermost: I[jl][y][x][c]; ~42 MB scratch.
__device__ float g_integral[(size_t)NJL * PLANE_S];

// ---------------------------------------------------------------------------
// Kernel A: per (jl, y=1..100): float4-load 21 channel rows into smem,
// serial x-cumsum per row (21 threads), coalesced transposed store (div-free).
// ---------------------------------------------------------------------------
__global__ void build_xsum(const float* __restrict__ in) {
    const int y   = blockIdx.x + 1;     // 1..100
    const int jl  = blockIdx.y;         // 0..48
    const int t   = threadIdx.x;
    const int wid = t >> 5, lane = t & 31;

    __shared__ float sm[C1 * HP];       // sm[c*101 + x], x = 0..99

    // Load: row c is 25 float4; warp w handles rows w, w+4, ... (no div/mod).
    const float4* src4 = (const float4*)(in + IN_BASE
                        + (size_t)jl * (C1 * H * W) + (size_t)(y - 1) * W);
    #pragma unroll
    for (int c = wid; c < C1; c += 4) {
        if (lane < 25) {
            float4 v = src4[c * (H * W / 4) + lane];
            float* d = sm + c * HP + lane * 4;
            d[0] = v.x; d[1] = v.y; d[2] = v.z; d[3] = v.w;
        }
    }
    __syncthreads();

    // x-cumsum: thread c scans its row (stride 101 -> conflict-free banks).
    if (t < C1) {
        float acc = 0.0f;
        float* r = sm + t * HP;
        #pragma unroll 10
        for (int x = 0; x < W; x++) { acc += r[x]; r[x] = acc; }
    }
    __syncthreads();

    // Store transposed row: 126 threads, c = t%21 / x0 = t/21 computed ONCE;
    // consecutive t -> consecutive addresses (fully coalesced, +126 per iter).
    float* outrow = g_integral + ((size_t)jl * HP + y) * ROW_S;
    if (t < 126) {
        const int c  = t % C1;
        const int x0 = t / C1;          // 0..5
        const float* rs = sm + c * HP;
        #pragma unroll
        for (int x = x0; x < HP; x += 6) {
            outrow[x * C1 + c] = (x == 0) ? 0.0f : rs[x - 1];
        }
    }
}

// ---------------------------------------------------------------------------
// Kernel B: y-cumsum over float4 slots (531 per row). Writes the y=0 zero row,
// then 100 dependent FADD4 steps; unroll 8 for load MLP. Pad lanes carry
// garbage but are never read by kernel C.
// ---------------------------------------------------------------------------
__global__ void build_ysum() {
    const int jl    = blockIdx.y;
    const int slot4 = blockIdx.x * blockDim.x + threadIdx.x;
    if (slot4 >= ROW_S / 4) return;

    float4* p = (float4*)(g_integral + (size_t)jl * PLANE_S) + slot4;
    const int stride4 = ROW_S / 4;      // 531

    float4 acc = make_float4(0.f, 0.f, 0.f, 0.f);
    p[0] = acc;                         // y = 0 row is zero
    #pragma unroll 8
    for (int y = 1; y <= H; y++) {
        float4 v = p[(size_t)y * stride4];
        acc.x += v.x; acc.y += v.y; acc.z += v.z; acc.w += v.w;
        p[(size_t)y * stride4] = acc;
    }
}

// ---------------------------------------------------------------------------
// Kernel C: one block per ROI. 336 active threads (16 jl-groups x 21 c),
// div-free mapping; 4 corner reads per (jl,c); deterministic reduction;
// warp softmax.
// ---------------------------------------------------------------------------
__global__ void pool_softmax(const int* __restrict__ rois,
                             float* __restrict__ out) {
    const int roi = blockIdx.x;
    const int t   = threadIdx.x;
    __shared__ float s_S[NJL * C1];
    __shared__ float s_avg[C1];

    const int4 r = ((const int4*)rois)[roi];   // ymin, xmin, ymax, xmax
    const int ys = (r.z - r.x) / KK;
    const int xs = (r.w - r.y) / KK;

    if (t < 336) {
        const int c   = t % C1;   // once per thread
        const int jl0 = t / C1;   // 0..15
        #pragma unroll
        for (int jl = jl0; jl < NJL; jl += 16) {
            const int j = jl / KK, l = jl - j * KK;
            const int y0 = r.x + j * ys, y1 = y0 + ys;
            const int x0 = r.y + l * xs, x1 = x0 + xs;
            const float* P = g_integral + (size_t)jl * PLANE_S;
            const float a = P[(size_t)y1 * ROW_S + x1 * C1 + c];
            const float b = P[(size_t)y0 * ROW_S + x1 * C1 + c];
            const float d = P[(size_t)y1 * ROW_S + x0 * C1 + c];
            const float e = P[(size_t)y0 * ROW_S + x0 * C1 + c];
            s_S[jl * C1 + c] = (a - b) - (d - e);
        }
    }
    __syncthreads();

    if (t < C1) {
        float acc = 0.0f;
        #pragma unroll 7
        for (int jl = 0; jl < NJL; jl++) acc += s_S[jl * C1 + t];
        s_avg[t] = acc / (49.0f * (float)(ys * xs));
    }
    __syncthreads();

    if (t < 32) {
        const bool act = t < C1;
        float v = act ? s_avg[t] : -INFINITY;
        float m = v;
        #pragma unroll
        for (int o = 16; o; o >>= 1) m = fmaxf(m, __shfl_xor_sync(0xffffffffu, m, o));
        float e = act ? expf(v - m) : 0.0f;
        float sum = e;
        #pragma unroll
        for (int o = 16; o; o >>= 1) sum += __shfl_xor_sync(0xffffffffu, sum, o);
        if (act) out[(size_t)roi * C1 + t] = e / sum;
    }
}

// ---------------------------------------------------------------------------
extern "C" void kernel_launch(void* const* d_in, const int* in_sizes, int n_in,
                              void* d_out, int out_size) {
    const float* x    = (const float*)d_in[0];
    const int*   rois = (const int*)d_in[1];
    float*       out  = (float*)d_out;
    const int n_rois  = in_sizes[1] / 4;   // 2000

    dim3 gA(H, NJL);                        // 100 x 49
    build_xsum<<<gA, 128>>>(x);

    dim3 gB((ROW_S / 4 + 127) / 128, NJL);  // 5 x 49
    build_ysum<<<gB, 128>>>();

    pool_softmax<<<n_rois, 352>>>(rois, out);
}

// round 6
// speedup vs baseline: 1.2598x; 1.0663x over previous
#include <cuda_runtime.h>
#include <cuda_bf16.h>
#include <math.h>

// Fixed shapes: cls_conv_out (4, 1029, 100, 100) fp32; rois (2000,4) int32.
// Only batch 3 used. Output (2000, 21, 1, 1) fp32.
#define KK       7
#define C1       21
#define NJL      49
#define H        100
#define W        100
#define HP       101
#define ROW_S    2124                 // HP*C1=2121 padded to mult of 4 (16B-aligned planes)
#define PLANE_S  (HP * ROW_S)
#define IN_BASE  (3 * 1029 * 10000)  // batch 3 offset

// Integral image, transposed c-innermost: I[jl][y][x][c]; ~42 MB scratch.
__device__ float g_integral[(size_t)NJL * PLANE_S];

// ---------------------------------------------------------------------------
// Kernel A: per (jl, y): global float4 load -> register shuffle-scan (x-cumsum)
// -> one smem pass (scan-result store, transpose read) -> coalesced global
// store of the transposed padded row.
// ---------------------------------------------------------------------------
__global__ void build_xsum(const float* __restrict__ in) {
    const int y    = blockIdx.x + 1;   // 1..100
    const int jl   = blockIdx.y;       // 0..48
    const int t    = threadIdx.x;
    const int w    = t >> 5, lane = t & 31;

    __shared__ float sm[C1 * HP];      // sm[c*101 + x] = inclusive cumsum at x

    // --- load: warp w owns channels {w, w+4, ...}; lanes 0..24 hold 1 float4
    const float4* src4 = (const float4*)(in + IN_BASE
                        + (size_t)jl * (C1 * H * W) + (size_t)(y - 1) * W);
    float4 v[6];
    #pragma unroll
    for (int k = 0; k < 6; k++) {
        const int c = w + 4 * k;
        if (c < C1 && lane < 25) v[k] = src4[c * (H * W / 4) + lane];
    }

    // --- scan each owned channel: in-thread scan of 4 + shfl_up scan over lanes
    #pragma unroll
    for (int k = 0; k < 6; k++) {
        const int c = w + 4 * k;
        if (c < C1) {
            float s0 = v[k].x;
            float s1 = s0 + v[k].y;
            float s2 = s1 + v[k].z;
            float s3 = s2 + v[k].w;
            float run = s3;
            #pragma unroll
            for (int d = 1; d < 32; d <<= 1) {
                float u = __shfl_up_sync(0xffffffffu, run, d);
                if (lane >= d) run += u;
            }
            const float off = run - s3;   // exclusive prefix of this lane's chunk
            if (lane < 25) {
                float* dst = sm + c * HP + 4 * lane;
                dst[0] = off + s0; dst[1] = off + s1;
                dst[2] = off + s2; dst[3] = off + s3;
            }
        }
    }
    __syncthreads();

    // --- transposed coalesced store: 126 threads, c/x0 computed once
    float* outrow = g_integral + ((size_t)jl * HP + y) * ROW_S;
    if (t < 126) {
        const int c  = t % C1;
        const int x0 = t / C1;          // 0..5
        const float* rs = sm + c * HP;
        #pragma unroll
        for (int x = x0; x < HP; x += 6) {
            outrow[x * C1 + c] = (x == 0) ? 0.0f : rs[x - 1];
        }
    }
}

// ---------------------------------------------------------------------------
// Kernel B: y-cumsum over float4 slots (531/row). Writes y=0 zero row, then
// 100 dependent FADD4 steps; unroll 10 for in-flight load MLP (only ~6
// warps/SM exist in this decomposition, so per-thread MLP is the lever).
// ---------------------------------------------------------------------------
__global__ void build_ysum() {
    const int jl    = blockIdx.y;
    const int slot4 = blockIdx.x * blockDim.x + threadIdx.x;
    if (slot4 >= ROW_S / 4) return;

    float4* p = (float4*)(g_integral + (size_t)jl * PLANE_S) + slot4;
    const int stride4 = ROW_S / 4;      // 531

    float4 acc = make_float4(0.f, 0.f, 0.f, 0.f);
    p[0] = acc;                         // y = 0 row is zero
    #pragma unroll 10
    for (int y = 1; y <= H; y++) {
        float4 v = p[(size_t)y * stride4];
        acc.x += v.x; acc.y += v.y; acc.z += v.z; acc.w += v.w;
        p[(size_t)y * stride4] = acc;
    }
}

// ---------------------------------------------------------------------------
// Kernel C: one block per ROI. 336 active threads (16 jl-groups x 21 c),
// div-free mapping; 4 corner reads per (jl,c); deterministic reduction;
// warp softmax.
// ---------------------------------------------------------------------------
__global__ void pool_softmax(const int* __restrict__ rois,
                             float* __restrict__ out) {
    const int roi = blockIdx.x;
    const int t   = threadIdx.x;
    __shared__ float s_S[NJL * C1];
    __shared__ float s_avg[C1];

    const int4 r = ((const int4*)rois)[roi];   // ymin, xmin, ymax, xmax
    const int ys = (r.z - r.x) / KK;
    const int xs = (r.w - r.y) / KK;

    if (t < 336) {
        const int c   = t % C1;
        const int jl0 = t / C1;   // 0..15
        #pragma unroll
        for (int jl = jl0; jl < NJL; jl += 16) {
            const int j = jl / KK, l = jl - j * KK;
            const int y0 = r.x + j * ys, y1 = y0 + ys;
            const int x0 = r.y + l * xs, x1 = x0 + xs;
            const float* P = g_integral + (size_t)jl * PLANE_S;
            const float a = P[(size_t)y1 * ROW_S + x1 * C1 + c];
            const float b = P[(size_t)y0 * ROW_S + x1 * C1 + c];
            const float d = P[(size_t)y1 * ROW_S + x0 * C1 + c];
            const float e = P[(size_t)y0 * ROW_S + x0 * C1 + c];
            s_S[jl * C1 + c] = (a - b) - (d - e);
        }
    }
    __syncthreads();

    if (t < C1) {
        float acc = 0.0f;
        #pragma unroll 7
        for (int jl = 0; jl < NJL; jl++) acc += s_S[jl * C1 + t];
        s_avg[t] = acc / (49.0f * (float)(ys * xs));
    }
    __syncthreads();

    if (t < 32) {
        const bool act = t < C1;
        float v = act ? s_avg[t] : -INFINITY;
        float m = v;
        #pragma unroll
        for (int o = 16; o; o >>= 1) m = fmaxf(m, __shfl_xor_sync(0xffffffffu, m, o));
        float e = act ? expf(v - m) : 0.0f;
        float sum = e;
        #pragma unroll
        for (int o = 16; o; o >>= 1) sum += __shfl_xor_sync(0xffffffffu, sum, o);
        if (act) out[(size_t)roi * C1 + t] = e / sum;
    }
}

// ---------------------------------------------------------------------------
extern "C" void kernel_launch(void* const* d_in, const int* in_sizes, int n_in,
                              void* d_out, int out_size) {
    const float* x    = (const float*)d_in[0];
    const int*   rois = (const int*)d_in[1];
    float*       out  = (float*)d_out;
    const int n_rois  = in_sizes[1] / 4;   // 2000

    dim3 gA(H, NJL);                        // 100 x 49
    build_xsum<<<gA, 128>>>(x);

    dim3 gB((ROW_S / 4 + 127) / 128, NJL);  // 5 x 49
    build_ysum<<<gB, 128>>>();

    pool_softmax<<<n_rois, 352>>>(rois, out);
}